// round 1
// baseline (speedup 1.0000x reference)
#include <cuda_runtime.h>

// Problem constants
#define NN     2048
#define MULS   128
#define DIN    9
#define NPAIR  45    // a<=b pairs of 9
#define NTRI   165   // a<=b<=c triples of 9

// Symmetrized, padded basis storage (float4-friendly):
//  A block:  9 rows * 4 cols   = 36 floats   (nu=1: [e0(1), e1(3)])
//  B block: 45 rows * 12 cols  = 540 floats  (nu=2: [e2 s0..2, e3 s0p0..s1p2], pad 3)
//  C block: 165 rows * 12 cols = 1980 floats (nu=3: [e4 s0..3, e5 s0p0..s1p2], pad 2)
#define OFF_A 0
#define OFF_B 36
#define OFF_C 576
#define BS_TOTAL 2556

__device__ float gBs[BS_TOTAL];

// ---------------------------------------------------------------------------
// Prep: symmetrize bases onto sorted multisets. One block, runs per launch.
// ---------------------------------------------------------------------------
__global__ void prep_kernel(const float* __restrict__ b0, const float* __restrict__ b1,
                            const float* __restrict__ b2, const float* __restrict__ b3,
                            const float* __restrict__ b4, const float* __restrict__ b5)
{
    const int t = threadIdx.x;

    // nu=1 rows (exactly 4 useful cols)
    if (t < DIN) {
        gBs[OFF_A + t * 4 + 0] = b0[t];
        gBs[OFF_A + t * 4 + 1] = b1[t * 3 + 0];
        gBs[OFF_A + t * 4 + 2] = b1[t * 3 + 1];
        gBs[OFF_A + t * 4 + 3] = b1[t * 3 + 2];
    }

    // nu=2 rows
    if (t < NPAIR) {
        int a = 0, b = 0, idx = 0;
        for (int i = 0; i < DIN; i++)
            for (int j = i; j < DIN; j++) {
                if (idx == t) { a = i; b = j; }
                idx++;
            }
        float* row = gBs + OFF_B + t * 12;
        for (int s = 0; s < 3; s++) {
            float v = b2[(a * 9 + b) * 3 + s];
            if (a != b) v += b2[(b * 9 + a) * 3 + s];
            row[s] = v;
        }
        for (int s = 0; s < 2; s++)
            for (int p = 0; p < 3; p++) {
                float v = b3[((a * 9 + b) * 2 + s) * 3 + p];
                if (a != b) v += b3[((b * 9 + a) * 2 + s) * 3 + p];
                row[3 + s * 3 + p] = v;
            }
        row[9] = 0.f; row[10] = 0.f; row[11] = 0.f;
    }

    // nu=3 rows
    if (t < NTRI) {
        int a = 0, b = 0, c = 0, idx = 0;
        for (int i = 0; i < DIN; i++)
            for (int j = i; j < DIN; j++)
                for (int k = j; k < DIN; k++) {
                    if (idx == t) { a = i; b = j; c = k; }
                    idx++;
                }
        // distinct permutations of (a,b,c)
        int pi[6] = {a, a, b, b, c, c};
        int pj[6] = {b, c, a, c, a, b};
        int pk[6] = {c, b, c, a, b, a};
        float acc[10];
        #pragma unroll
        for (int q = 0; q < 10; q++) acc[q] = 0.f;

        for (int q = 0; q < 6; q++) {
            bool dup = false;
            for (int r = 0; r < q; r++)
                if (pi[r] == pi[q] && pj[r] == pj[q] && pk[r] == pk[q]) { dup = true; break; }
            if (dup) continue;
            const int base = (pi[q] * 9 + pj[q]) * 9 + pk[q];
            for (int s = 0; s < 4; s++) acc[s] += b4[base * 4 + s];
            for (int s = 0; s < 2; s++)
                for (int p = 0; p < 3; p++)
                    acc[4 + s * 3 + p] += b5[(base * 2 + s) * 3 + p];
        }
        float* row = gBs + OFF_C + t * 12;
        #pragma unroll
        for (int q = 0; q < 10; q++) row[q] = acc[q];
        row[10] = 0.f; row[11] = 0.f;
    }
}

// ---------------------------------------------------------------------------
// Main kernel: one thread per (node, mul). blockDim = (128, 2).
// ---------------------------------------------------------------------------
__global__ void __launch_bounds__(256)
symcon_kernel(const float* __restrict__ feats,   // (N, 1152)
              const int*   __restrict__ species, // (N,)
              const float* __restrict__ W0, const float* __restrict__ W1,
              const float* __restrict__ W2, const float* __restrict__ W3,
              const float* __restrict__ W4, const float* __restrict__ W5,
              float* __restrict__ out)            // (N, 512)
{
    __shared__ float4 s4[BS_TOTAL / 4];   // 639 float4 = 10224 B

    const int tid = threadIdx.y * 128 + threadIdx.x;
    {
        const float4* g4 = reinterpret_cast<const float4*>(gBs);
        #pragma unroll
        for (int i = tid; i < BS_TOTAL / 4; i += 256) s4[i] = g4[i];
    }
    __syncthreads();

    const float4* sA = s4;            // 9 float4
    const float4* sB = s4 + 9;        // 135 float4
    const float4* sC = s4 + 9 + 135;  // 495 float4

    const int m = threadIdx.x;
    const int n = blockIdx.x * 2 + threadIdx.y;
    const int e = species[n];

    const float* fbase = feats + n * 1152;

    // gather f (per-mul 9-vector: l0(1) + l1(3) + l2(5))
    float f[9];
    f[0] = fbase[m];
    #pragma unroll
    for (int k = 0; k < 3; k++) f[1 + k] = fbase[128 + m * 3 + k];
    #pragma unroll
    for (int k = 0; k < 5; k++) f[4 + k] = fbase[512 + m * 5 + k];

    // pair products (a<=b), same enumeration order as prep
    float P[NPAIR];
    {
        int q = 0;
        #pragma unroll
        for (int a = 0; a < 9; a++)
            #pragma unroll
            for (int b = a; b < 9; b++) { P[q] = f[a] * f[b]; q++; }
    }

    // nu=1: TA[4]
    float TA[4] = {0.f, 0.f, 0.f, 0.f};
    #pragma unroll
    for (int a = 0; a < 9; a++) {
        const float4 v = sA[a];
        const float fa = f[a];
        TA[0] = fmaf(v.x, fa, TA[0]);
        TA[1] = fmaf(v.y, fa, TA[1]);
        TA[2] = fmaf(v.z, fa, TA[2]);
        TA[3] = fmaf(v.w, fa, TA[3]);
    }

    // nu=2: TB[9]
    float TB[9];
    #pragma unroll
    for (int q = 0; q < 9; q++) TB[q] = 0.f;
    {
        int t2 = 0;
        #pragma unroll
        for (int a = 0; a < 9; a++)
            #pragma unroll
            for (int b = a; b < 9; b++) {
                const float Fv = P[t2];
                const float4 v0 = sB[3 * t2 + 0];
                const float4 v1 = sB[3 * t2 + 1];
                const float4 v2 = sB[3 * t2 + 2];
                TB[0] = fmaf(v0.x, Fv, TB[0]);
                TB[1] = fmaf(v0.y, Fv, TB[1]);
                TB[2] = fmaf(v0.z, Fv, TB[2]);
                TB[3] = fmaf(v0.w, Fv, TB[3]);
                TB[4] = fmaf(v1.x, Fv, TB[4]);
                TB[5] = fmaf(v1.y, Fv, TB[5]);
                TB[6] = fmaf(v1.z, Fv, TB[6]);
                TB[7] = fmaf(v1.w, Fv, TB[7]);
                TB[8] = fmaf(v2.x, Fv, TB[8]);
                t2++;
            }
    }

    // nu=3: TC[10]
    float TC[10];
    #pragma unroll
    for (int q = 0; q < 10; q++) TC[q] = 0.f;
    {
        int t3 = 0;
        int pr = 0;
        #pragma unroll
        for (int a = 0; a < 9; a++) {
            #pragma unroll
            for (int b = a; b < 9; b++) {
                const float Pab = P[pr];
                #pragma unroll
                for (int c = b; c < 9; c++) {
                    const float Fv = Pab * f[c];
                    const float4 v0 = sC[3 * t3 + 0];
                    const float4 v1 = sC[3 * t3 + 1];
                    const float4 v2 = sC[3 * t3 + 2];
                    TC[0] = fmaf(v0.x, Fv, TC[0]);
                    TC[1] = fmaf(v0.y, Fv, TC[1]);
                    TC[2] = fmaf(v0.z, Fv, TC[2]);
                    TC[3] = fmaf(v0.w, Fv, TC[3]);
                    TC[4] = fmaf(v1.x, Fv, TC[4]);
                    TC[5] = fmaf(v1.y, Fv, TC[5]);
                    TC[6] = fmaf(v1.z, Fv, TC[6]);
                    TC[7] = fmaf(v1.w, Fv, TC[7]);
                    TC[8] = fmaf(v2.x, Fv, TC[8]);
                    TC[9] = fmaf(v2.y, Fv, TC[9]);
                    t3++;
                }
                pr++;
            }
        }
    }

    // weight contraction (per-species gather, coalesced over m)
    float o0;
    {
        o0 = W0[e * 128 + m] * TA[0];
        #pragma unroll
        for (int s = 0; s < 3; s++) o0 = fmaf(W2[(e * 3 + s) * 128 + m], TB[s], o0);
        #pragma unroll
        for (int s = 0; s < 4; s++) o0 = fmaf(W4[(e * 4 + s) * 128 + m], TC[s], o0);
    }
    float o1[3];
    {
        const float w1 = W1[e * 128 + m];
        #pragma unroll
        for (int p = 0; p < 3; p++) o1[p] = w1 * TA[1 + p];
        #pragma unroll
        for (int s = 0; s < 2; s++) {
            const float w = W3[(e * 2 + s) * 128 + m];
            #pragma unroll
            for (int p = 0; p < 3; p++) o1[p] = fmaf(w, TB[3 + s * 3 + p], o1[p]);
        }
        #pragma unroll
        for (int s = 0; s < 2; s++) {
            const float w = W5[(e * 2 + s) * 128 + m];
            #pragma unroll
            for (int p = 0; p < 3; p++) o1[p] = fmaf(w, TC[4 + s * 3 + p], o1[p]);
        }
    }

    // output: (N, 512) = [l0: (N,128)] ++ [l1: (N,128,3)]
    float* obase = out + n * 512;
    obase[m] = o0;
    #pragma unroll
    for (int p = 0; p < 3; p++) obase[128 + m * 3 + p] = o1[p];
}

// ---------------------------------------------------------------------------
extern "C" void kernel_launch(void* const* d_in, const int* in_sizes, int n_in,
                              void* d_out, int out_size)
{
    const float* feats   = (const float*)d_in[0];
    const int*   species = (const int*)  d_in[1];
    const float* b0 = (const float*)d_in[2];
    const float* w0 = (const float*)d_in[3];
    const float* b1 = (const float*)d_in[4];
    const float* w1 = (const float*)d_in[5];
    const float* b2 = (const float*)d_in[6];
    const float* w2 = (const float*)d_in[7];
    const float* b3 = (const float*)d_in[8];
    const float* w3 = (const float*)d_in[9];
    const float* b4 = (const float*)d_in[10];
    const float* w4 = (const float*)d_in[11];
    const float* b5 = (const float*)d_in[12];
    const float* w5 = (const float*)d_in[13];
    float* out = (float*)d_out;

    prep_kernel<<<1, 256>>>(b0, b1, b2, b3, b4, b5);

    dim3 block(128, 2);
    dim3 grid(NN / 2);
    symcon_kernel<<<grid, block>>>(feats, species, w0, w1, w2, w3, w4, w5, out);
}